// round 2
// baseline (speedup 1.0000x reference)
#include <cuda_runtime.h>
#include <math.h>

#define NN  128000   // B*NPG nodes
#define EE  2048000  // B*EPG edges
#define BBG 128      // graphs
#define NPG 1000
#define EPG 16000
#define DD  128
#define KK  64

// ---------------- scratch (static device globals; no allocs) ----------------
__device__ int   g_deg[NN];
__device__ float g_dinv[NN];
__device__ int   g_rowptr[NN];      // absolute start into g_csr_src
__device__ int   g_csr_src[EE];     // graph-LOCAL src index per (dst-sorted) edge
__device__ float g_bufA[(size_t)NN * DD];
__device__ float g_bufB[(size_t)NN * DD];
__device__ float g_pool[BBG * DD];

// ---------------- f32x2 helpers ----------------
__device__ __forceinline__ void fma2(unsigned long long& d, unsigned long long a,
                                     unsigned long long b) {
    asm("fma.rn.f32x2 %0, %1, %2, %0;" : "+l"(d) : "l"(a), "l"(b));
}
__device__ __forceinline__ unsigned long long pack2(float x) {
    unsigned long long r;
    unsigned u = __float_as_uint(x);
    asm("mov.b64 %0, {%1, %1};" : "=l"(r) : "r"(u));
    return r;
}
__device__ __forceinline__ float2 unpack2(unsigned long long v) {
    unsigned lo, hi;
    asm("mov.b64 {%0, %1}, %2;" : "=r"(lo), "=r"(hi) : "l"(v));
    return make_float2(__uint_as_float(lo), __uint_as_float(hi));
}

// ---------------- fused CSR build: one CTA per graph ----------------
// Pass 1: smem histogram of in-degree. Scan. Pass 2: smem-cursor scatter fill.
__global__ __launch_bounds__(1024) void k_build(const int* __restrict__ src,
                                                const int* __restrict__ dst) {
    __shared__ int cnt[NPG];
    __shared__ int ws[32];
    int b = blockIdx.x;
    int t = threadIdx.x;
    int ebase = b * EPG;
    int nbase = b * NPG;

    if (t < NPG) cnt[t] = 0;
    __syncthreads();

    for (int e = t; e < EPG; e += 1024)
        atomicAdd(&cnt[dst[ebase + e] - nbase], 1);
    __syncthreads();

    int val = (t < NPG) ? cnt[t] : 0;

    // block exclusive scan over 1024 lanes
    int x = val;
    unsigned m = 0xffffffffu;
    #pragma unroll
    for (int o = 1; o < 32; o <<= 1) {
        int y = __shfl_up_sync(m, x, o);
        if ((t & 31) >= o) x += y;
    }
    if ((t & 31) == 31) ws[t >> 5] = x;
    __syncthreads();
    if (t < 32) {
        int y = ws[t];
        int z = y;
        #pragma unroll
        for (int o = 1; o < 32; o <<= 1) {
            int w = __shfl_up_sync(m, z, o);
            if (t >= o) z += w;
        }
        ws[t] = z - y;  // exclusive prefix of warp sums
    }
    __syncthreads();
    int excl = x + ws[t >> 5] - val;
    __syncthreads();  // everyone done reading cnt[] as counts

    if (t < NPG) {
        int v = nbase + t;
        g_deg[v]    = val;
        g_rowptr[v] = ebase + excl;
        g_dinv[v]   = rsqrtf((float)(val + 1));  // +1 self-loop
        cnt[t] = excl;                            // becomes the cursor
    }
    __syncthreads();

    for (int e = t; e < EPG; e += 1024) {
        int s = src[ebase + e] - nbase;
        int d = dst[ebase + e] - nbase;
        int p = atomicAdd(&cnt[d], 1);
        g_csr_src[ebase + p] = s;
    }
}

// ---------------- GEMM (f32x2): O[r,:] = dinv[r] * (X[r,:] @ W) ----------------
// 256 threads, 64-row tile. W (64KB) + X tile (32KB) in smem = 96KB dynamic.
// Thread (tx = t&15, ty = t>>4): cols tx*8..tx*8+7, rows ty*4..ty*4+3.
__global__ __launch_bounds__(256) void k_gemm128(const float* __restrict__ X,
                                                 const float* __restrict__ W,
                                                 float* __restrict__ O) {
    extern __shared__ float sm[];
    float* sW = sm;             // 128*128
    float* sX = sm + DD * DD;   // 64*128
    int t = threadIdx.x;
    size_t row0 = (size_t)blockIdx.x * 64;

    const float4* W4 = (const float4*)W;
    float4* sW4 = (float4*)sW;
    #pragma unroll
    for (int i = t; i < DD * DD / 4; i += 256) sW4[i] = W4[i];
    const float4* X4 = (const float4*)(X + row0 * DD);
    float4* sX4 = (float4*)sX;
    #pragma unroll
    for (int i = t; i < 64 * DD / 4; i += 256) sX4[i] = X4[i];
    __syncthreads();

    int tx = t & 15;
    int ty = t >> 4;

    unsigned long long acc[4][4];
    #pragma unroll
    for (int r = 0; r < 4; r++)
        #pragma unroll
        for (int j = 0; j < 4; j++) acc[r][j] = 0ull;

    const ulonglong2* sW2 = (const ulonglong2*)sW;
    const float* xb = sX + (ty * 4) * DD;

    #pragma unroll 4
    for (int k0 = 0; k0 < DD; k0 += 4) {
        float4 xr[4];
        #pragma unroll
        for (int r = 0; r < 4; r++) xr[r] = *(const float4*)&xb[r * DD + k0];
        #pragma unroll
        for (int kk = 0; kk < 4; kk++) {
            ulonglong2 wa = sW2[(k0 + kk) * 32 + tx * 2];
            ulonglong2 wb = sW2[(k0 + kk) * 32 + tx * 2 + 1];
            #pragma unroll
            for (int r = 0; r < 4; r++) {
                float xs = (kk == 0) ? xr[r].x : (kk == 1) ? xr[r].y
                         : (kk == 2) ? xr[r].z : xr[r].w;
                unsigned long long xp = pack2(xs);
                fma2(acc[r][0], xp, wa.x);
                fma2(acc[r][1], xp, wa.y);
                fma2(acc[r][2], xp, wb.x);
                fma2(acc[r][3], xp, wb.y);
            }
        }
    }

    #pragma unroll
    for (int r = 0; r < 4; r++) {
        size_t row = row0 + ty * 4 + r;
        float dv = g_dinv[row];
        float2 p0 = unpack2(acc[r][0]);
        float2 p1 = unpack2(acc[r][1]);
        float2 p2 = unpack2(acc[r][2]);
        float2 p3 = unpack2(acc[r][3]);
        float4 o0 = make_float4(dv * p0.x, dv * p0.y, dv * p1.x, dv * p1.y);
        float4 o1 = make_float4(dv * p2.x, dv * p2.y, dv * p3.x, dv * p3.y);
        float* orow = O + row * DD + tx * 8;
        *(float4*)orow = o0;
        *(float4*)(orow + 4) = o1;
    }
}

// ---------------- aggregation (smem-tiled) ----------------
// grid (BBG, 4). CTA loads graph b's XW' slice for dims [q*32, q*32+32) into
// smem (1000x32 fp32 = 125KB), then each warp gathers per-node sums from smem.
// OUT[v, dims] = relu(dinv[v] * (sum_{s in in(v)} XW'[s] + XW'[v]) + bias)
__global__ __launch_bounds__(1024) void k_agg(const float* __restrict__ XW,
                                              float* __restrict__ OUT,
                                              const float* __restrict__ bias) {
    extern __shared__ float s_x[];  // [1000][32]
    int b = blockIdx.x;
    int q = blockIdx.y;
    int t = threadIdx.x;
    int nbase = b * NPG;

    // load slice: 1000 rows x 8 float4
    for (int idx = t; idx < NPG * 8; idx += 1024) {
        int row = idx >> 3;
        int c4 = idx & 7;
        *(float4*)&s_x[row * 32 + c4 * 4] =
            *(const float4*)&XW[(size_t)(nbase + row) * DD + q * 32 + c4 * 4];
    }
    __syncthreads();

    int warp = t >> 5;
    int lane = t & 31;
    float bb = bias[q * 32 + lane];

    for (int vl = warp; vl < NPG; vl += 32) {
        int v = nbase + vl;
        int start = g_rowptr[v];
        int cnt = g_deg[v];
        float acc = s_x[vl * 32 + lane];  // self-loop term

        for (int base = 0; base < cnt; base += 32) {
            int idx = base + lane;
            int s = (idx < cnt) ? g_csr_src[start + idx] : 0;
            int mcnt = min(32, cnt - base);
            int j = 0;
            for (; j + 4 <= mcnt; j += 4) {
                #pragma unroll
                for (int u = 0; u < 4; u++) {
                    int sj = __shfl_sync(0xffffffffu, s, j + u);
                    acc += s_x[sj * 32 + lane];
                }
            }
            for (; j < mcnt; j++) {
                int sj = __shfl_sync(0xffffffffu, s, j);
                acc += s_x[sj * 32 + lane];
            }
        }

        float res = fmaxf(g_dinv[v] * acc + bb, 0.f);
        OUT[(size_t)v * DD + q * 32 + lane] = res;
    }
}

// ---------------- per-graph mean pool / K ----------------
__global__ void k_pool(const float* __restrict__ NE) {
    int b = blockIdx.x;
    int t = threadIdx.x;
    int dd = t & 127;
    int q = t >> 7;  // 0..3
    const float* base = NE + (size_t)b * NPG * DD + dd;
    float s = 0.f;
    int r0 = q * (NPG / 4);
    #pragma unroll 4
    for (int r = 0; r < NPG / 4; r++) s += base[(size_t)(r0 + r) * DD];
    __shared__ float sm[512];
    sm[t] = s;
    __syncthreads();
    if (q == 0) {
        float tot = sm[dd] + sm[dd + 128] + sm[dd + 256] + sm[dd + 384];
        g_pool[b * DD + dd] = tot * (1.0f / KK);
    }
}

// ---------------- final MLP ----------------
__global__ void k_mlp(const float* __restrict__ W1, const float* __restrict__ b1,
                      const float* __restrict__ W2, const float* __restrict__ b2,
                      float* __restrict__ out) {
    int b = blockIdx.x;
    int t = threadIdx.x;  // 128
    __shared__ float p[128], h[128];
    p[t] = g_pool[b * 128 + t];
    __syncthreads();
    float acc = b1[t];
    #pragma unroll 4
    for (int d = 0; d < 128; d++) acc += p[d] * W1[d * 128 + t];
    h[t] = fmaxf(acc, 0.f);
    __syncthreads();
    if (t < 10) {
        float o = b2[t];
        #pragma unroll 4
        for (int j = 0; j < 128; j++) o += h[j] * W2[j * 10 + t];
        out[b * 10 + t] = o;
    }
}

// ---------------- launch ----------------
extern "C" void kernel_launch(void* const* d_in, const int* in_sizes, int n_in,
                              void* d_out, int out_size) {
    const float* x     = (const float*)d_in[0];
    const int*   ei    = (const int*)d_in[1];
    const float* W_pre = (const float*)d_in[3];
    const float* b_pre = (const float*)d_in[4];
    const float* W_emb = (const float*)d_in[5];
    const float* b_emb = (const float*)d_in[6];
    // d_in[2] batch, d_in[7] W_asn, d_in[8] b_asn dead (softmax rows sum to 1)
    const float* W1 = (const float*)d_in[9];
    const float* b1 = (const float*)d_in[10];
    const float* W2 = (const float*)d_in[11];
    const float* b2 = (const float*)d_in[12];
    float* out = (float*)d_out;

    int E = in_sizes[1] / 2;
    int N = in_sizes[0] / DD;
    const int* src = ei;
    const int* dst = ei + E;

    void *pA, *pB;
    cudaGetSymbolAddress(&pA, g_bufA);
    cudaGetSymbolAddress(&pB, g_bufB);
    float* bufA = (float*)pA;
    float* bufB = (float*)pB;

    const int smem_gemm = (DD * DD + 64 * DD) * (int)sizeof(float);  // 96KB
    const int smem_agg = NPG * 32 * (int)sizeof(float);              // 125KB
    static int attr_done = 0;
    cudaFuncSetAttribute(k_gemm128, cudaFuncAttributeMaxDynamicSharedMemorySize, smem_gemm);
    cudaFuncSetAttribute(k_agg, cudaFuncAttributeMaxDynamicSharedMemorySize, smem_agg);
    (void)attr_done;

    // normalized-adjacency CSR build (per-graph, smem histogram + scan + fill)
    k_build<<<BBG, 1024>>>(src, dst);

    // conv1: h = relu(Ahat @ (x @ W_pre) + b_pre)   [dinv folded into GEMM rows]
    k_gemm128<<<N / 64, 256, smem_gemm>>>(x, W_pre, bufA);
    k_agg<<<dim3(BBG, 4), 1024, smem_agg>>>(bufA, bufB, b_pre);

    // conv2: NE = relu(Ahat @ (h @ W_emb) + b_emb)
    k_gemm128<<<N / 64, 256, smem_gemm>>>(bufB, W_emb, bufA);
    k_agg<<<dim3(BBG, 4), 1024, smem_agg>>>(bufA, bufB, b_emb);

    // pool (assignment branch collapses to mean/K) + MLP head
    k_pool<<<BBG, 512>>>(bufB);
    k_mlp<<<BBG, 128>>>(W1, b1, W2, b2, out);
}

// round 4
// speedup vs baseline: 1.6617x; 1.6617x over previous
#include <cuda_runtime.h>
#include <math.h>
#include <stdint.h>

#define NN  128000   // B*NPG nodes
#define EE  2048000  // B*EPG edges
#define BBG 128      // graphs
#define NPG 1000
#define EPG 16000
#define DD  128
#define KK  64

// ---------------- scratch (static device globals; no allocs) ----------------
__device__ int   g_deg[NN];
__device__ float g_dinv[NN];
__device__ int   g_rowptr[NN];      // absolute start into g_csr_src
__device__ int   g_csr_src[EE];     // graph-LOCAL src index per (dst-sorted) edge
__device__ float g_bufA[(size_t)NN * DD];
__device__ float g_bufB[(size_t)NN * DD];
__device__ float g_pool[BBG * DD];

// ---------------- f32x2 helpers (verified working on this toolchain in R2) ----
__device__ __forceinline__ void fma2(unsigned long long& d, unsigned long long a,
                                     unsigned long long b) {
    asm("fma.rn.f32x2 %0, %1, %2, %0;" : "+l"(d) : "l"(a), "l"(b));
}
__device__ __forceinline__ unsigned long long pack2(float x) {
    unsigned long long r;
    unsigned u = __float_as_uint(x);
    asm("mov.b64 %0, {%1, %1};" : "=l"(r) : "r"(u));
    return r;
}
__device__ __forceinline__ float2 unpack2(unsigned long long v) {
    unsigned lo, hi;
    asm("mov.b64 {%0, %1}, %2;" : "=r"(lo), "=r"(hi) : "l"(v));
    return make_float2(__uint_as_float(lo), __uint_as_float(hi));
}

// ---------------- fused CSR build: one CTA per graph (proven R2) ----------------
__global__ __launch_bounds__(1024) void k_build(const int* __restrict__ src,
                                                const int* __restrict__ dst) {
    __shared__ int cnt[NPG];
    __shared__ int ws[32];
    int b = blockIdx.x;
    int t = threadIdx.x;
    int ebase = b * EPG;
    int nbase = b * NPG;

    if (t < NPG) cnt[t] = 0;
    __syncthreads();

    for (int e = t; e < EPG; e += 1024)
        atomicAdd(&cnt[dst[ebase + e] - nbase], 1);
    __syncthreads();

    int val = (t < NPG) ? cnt[t] : 0;
    int x = val;
    unsigned m = 0xffffffffu;
    #pragma unroll
    for (int o = 1; o < 32; o <<= 1) {
        int y = __shfl_up_sync(m, x, o);
        if ((t & 31) >= o) x += y;
    }
    if ((t & 31) == 31) ws[t >> 5] = x;
    __syncthreads();
    if (t < 32) {
        int y = ws[t];
        int z = y;
        #pragma unroll
        for (int o = 1; o < 32; o <<= 1) {
            int w = __shfl_up_sync(m, z, o);
            if (t >= o) z += w;
        }
        ws[t] = z - y;
    }
    __syncthreads();
    int excl = x + ws[t >> 5] - val;
    __syncthreads();

    if (t < NPG) {
        int v = nbase + t;
        g_deg[v]    = val;
        g_rowptr[v] = ebase + excl;
        g_dinv[v]   = rsqrtf((float)(val + 1));  // +1 self-loop
        cnt[t] = excl;
    }
    __syncthreads();

    for (int e = t; e < EPG; e += 1024) {
        int s = src[ebase + e] - nbase;
        int d = dst[ebase + e] - nbase;
        int p = atomicAdd(&cnt[d], 1);
        g_csr_src[ebase + p] = s;
    }
}

// ---------------- GEMM (f32x2, col-pair accumulators) --------------------------
// O[r,:] = dinv[r] * (X[r,:] @ W).  128-row tiles, 512 threads.
// smem: sW [128][128] plain row-major (64KB) + sX [128][130] padded (65KB).
// Warp = 32 rows x 32 cols of the tile; thread = 4 rows x 8 cols.
// acc[i][cp] = f32x2 {out[r0+i][c0+2cp], out[r0+i][c0+2cp+1]}
//   fma2(acc, dup(x[r][k]), natural-pair {W[k][c], W[k][c+1]})
#define XPAD 130

__global__ __launch_bounds__(512) void k_gemm(const float* __restrict__ X,
                                              const float* __restrict__ W,
                                              float* __restrict__ O) {
    extern __shared__ float sm[];
    float* sW = sm;                 // 128*128
    float* sX = sm + DD * DD;       // 128*130
    int t = threadIdx.x;
    size_t row0 = (size_t)blockIdx.x * 128;

    // load W (plain row-major)
    const float4* W4 = (const float4*)W;
    float4* sW4 = (float4*)sW;
    #pragma unroll
    for (int i = t; i < DD * DD / 4; i += 512) sW4[i] = W4[i];

    // load X tile, rows padded to 130 floats
    const float4* X4 = (const float4*)(X + row0 * DD);
    #pragma unroll
    for (int i = 0; i < 8; i++) {
        int gid = i * 512 + t;           // 4096 float4 groups: 128 rows x 32
        int r = gid >> 5, c4 = gid & 31;
        float4 v = X4[gid];
        float2* p = (float2*)&sX[r * XPAD + c4 * 4];
        p[0] = make_float2(v.x, v.y);
        p[1] = make_float2(v.z, v.w);
    }
    __syncthreads();

    int w = t >> 5, lane = t & 31;
    int wr = w & 3, wc = w >> 2;     // 4 row-groups x 4 col-groups of warps
    int lr = lane >> 2, lc = lane & 3;
    int r0 = wr * 32 + lr * 4;       // rows r0..r0+3
    int c0 = wc * 32 + lc * 8;       // cols c0..c0+7

    unsigned long long acc[4][4];
    #pragma unroll
    for (int i = 0; i < 4; i++)
        #pragma unroll
        for (int j = 0; j < 4; j++) acc[i][j] = 0ull;

    const ulonglong2* sWp = (const ulonglong2*)sW;  // 16B = 4 cols = 2 col-pairs
    int widx = c0 >> 2;

    #pragma unroll 4
    for (int k = 0; k < DD; k += 2) {
        float2 xa[4];
        #pragma unroll
        for (int i = 0; i < 4; i++)
            xa[i] = *(const float2*)&sX[(r0 + i) * XPAD + k];
        ulonglong2 wA0 = sWp[k * 32 + widx];
        ulonglong2 wA1 = sWp[k * 32 + widx + 1];
        ulonglong2 wB0 = sWp[(k + 1) * 32 + widx];
        ulonglong2 wB1 = sWp[(k + 1) * 32 + widx + 1];
        #pragma unroll
        for (int i = 0; i < 4; i++) {
            unsigned long long ad = pack2(xa[i].x);
            fma2(acc[i][0], ad, wA0.x);
            fma2(acc[i][1], ad, wA0.y);
            fma2(acc[i][2], ad, wA1.x);
            fma2(acc[i][3], ad, wA1.y);
        }
        #pragma unroll
        for (int i = 0; i < 4; i++) {
            unsigned long long ad = pack2(xa[i].y);
            fma2(acc[i][0], ad, wB0.x);
            fma2(acc[i][1], ad, wB0.y);
            fma2(acc[i][2], ad, wB1.x);
            fma2(acc[i][3], ad, wB1.y);
        }
    }

    #pragma unroll
    for (int i = 0; i < 4; i++) {
        size_t row = row0 + r0 + i;
        float dv = g_dinv[row];
        float2 p0 = unpack2(acc[i][0]);
        float2 p1 = unpack2(acc[i][1]);
        float2 p2 = unpack2(acc[i][2]);
        float2 p3 = unpack2(acc[i][3]);
        float4 o0 = make_float4(dv * p0.x, dv * p0.y, dv * p1.x, dv * p1.y);
        float4 o1 = make_float4(dv * p2.x, dv * p2.y, dv * p3.x, dv * p3.y);
        *(float4*)&O[row * DD + c0] = o0;
        *(float4*)&O[row * DD + c0 + 4] = o1;
    }
}

// ---------------- aggregation (L2 gather; proven R1 structure) ----------------
// OUT[v,:] = relu(dinv[v] * (sum_{s in in(v)} XW'[s,:] + XW'[v,:]) + bias)
// where XW' rows are pre-scaled by dinv[src] in the GEMM epilogue.
__global__ __launch_bounds__(256) void k_agg(const float* __restrict__ XW,
                                             float* __restrict__ OUT,
                                             const float* __restrict__ bias) {
    int warp = (blockIdx.x * blockDim.x + threadIdx.x) >> 5;
    int lane = threadIdx.x & 31;
    if (warp >= NN) return;
    int v = warp;
    int nbase = (v / NPG) * NPG;

    const float4* X4 = (const float4*)XW;
    float4 acc = X4[(size_t)v * 32 + lane];   // self-loop term

    int start = g_rowptr[v];
    int cnt = g_deg[v];
    for (int base = 0; base < cnt; base += 32) {
        int idx = base + lane;
        int s = (idx < cnt) ? g_csr_src[start + idx] : 0;
        int mcnt = min(32, cnt - base);
        int j = 0;
        for (; j + 4 <= mcnt; j += 4) {
            #pragma unroll
            for (int u = 0; u < 4; u++) {
                int sj = __shfl_sync(0xffffffffu, s, j + u);
                float4 xs = X4[(size_t)(nbase + sj) * 32 + lane];
                acc.x += xs.x; acc.y += xs.y; acc.z += xs.z; acc.w += xs.w;
            }
        }
        for (; j < mcnt; j++) {
            int sj = __shfl_sync(0xffffffffu, s, j);
            float4 xs = X4[(size_t)(nbase + sj) * 32 + lane];
            acc.x += xs.x; acc.y += xs.y; acc.z += xs.z; acc.w += xs.w;
        }
    }

    float dv = g_dinv[v];
    float4 bb = ((const float4*)bias)[lane];
    float4 res = make_float4(fmaxf(dv * acc.x + bb.x, 0.f),
                             fmaxf(dv * acc.y + bb.y, 0.f),
                             fmaxf(dv * acc.z + bb.z, 0.f),
                             fmaxf(dv * acc.w + bb.w, 0.f));
    ((float4*)OUT)[(size_t)v * 32 + lane] = res;
}

// ---------------- per-graph mean pool / K ----------------
__global__ void k_pool(const float* __restrict__ NE) {
    int b = blockIdx.x;
    int t = threadIdx.x;
    int dd = t & 127;
    int q = t >> 7;
    const float* base = NE + (size_t)b * NPG * DD + dd;
    float s = 0.f;
    int r0 = q * (NPG / 4);
    #pragma unroll 4
    for (int r = 0; r < NPG / 4; r++) s += base[(size_t)(r0 + r) * DD];
    __shared__ float sm[512];
    sm[t] = s;
    __syncthreads();
    if (q == 0) {
        float tot = sm[dd] + sm[dd + 128] + sm[dd + 256] + sm[dd + 384];
        g_pool[b * DD + dd] = tot * (1.0f / KK);
    }
}

// ---------------- final MLP ----------------
__global__ void k_mlp(const float* __restrict__ W1, const float* __restrict__ b1,
                      const float* __restrict__ W2, const float* __restrict__ b2,
                      float* __restrict__ out) {
    int b = blockIdx.x;
    int t = threadIdx.x;
    __shared__ float p[128], h[128];
    p[t] = g_pool[b * 128 + t];
    __syncthreads();
    float acc = b1[t];
    #pragma unroll 4
    for (int d = 0; d < 128; d++) acc += p[d] * W1[d * 128 + t];
    h[t] = fmaxf(acc, 0.f);
    __syncthreads();
    if (t < 10) {
        float o = b2[t];
        #pragma unroll 4
        for (int j = 0; j < 128; j++) o += h[j] * W2[j * 10 + t];
        out[b * 10 + t] = o;
    }
}

// ---------------- launch ----------------
extern "C" void kernel_launch(void* const* d_in, const int* in_sizes, int n_in,
                              void* d_out, int out_size) {
    const float* x     = (const float*)d_in[0];
    const int*   ei    = (const int*)d_in[1];
    const float* W_pre = (const float*)d_in[3];
    const float* b_pre = (const float*)d_in[4];
    const float* W_emb = (const float*)d_in[5];
    const float* b_emb = (const float*)d_in[6];
    // d_in[2] batch, d_in[7] W_asn, d_in[8] b_asn dead (softmax rows sum to 1)
    const float* W1 = (const float*)d_in[9];
    const float* b1 = (const float*)d_in[10];
    const float* W2 = (const float*)d_in[11];
    const float* b2 = (const float*)d_in[12];
    float* out = (float*)d_out;

    int E = in_sizes[1] / 2;
    int N = in_sizes[0] / DD;
    const int* src = ei;
    const int* dst = ei + E;

    void *pA, *pB;
    cudaGetSymbolAddress(&pA, g_bufA);
    cudaGetSymbolAddress(&pB, g_bufB);
    float* bufA = (float*)pA;
    float* bufB = (float*)pB;

    const int smem_gemm = (DD * DD + DD * XPAD) * (int)sizeof(float);  // 132096B
    cudaFuncSetAttribute(k_gemm, cudaFuncAttributeMaxDynamicSharedMemorySize, smem_gemm);

    // normalized-adjacency CSR build (per-graph, smem histogram + scan + fill)
    k_build<<<BBG, 1024>>>(src, dst);

    // conv1: h = relu(Ahat @ (x @ W_pre) + b_pre)   [dinv folded into GEMM rows]
    k_gemm<<<N / 128, 512, smem_gemm>>>(x, W_pre, bufA);
    k_agg<<<N / 8, 256>>>(bufA, bufB, b_pre);

    // conv2: NE = relu(Ahat @ (h @ W_emb) + b_emb)
    k_gemm<<<N / 128, 512, smem_gemm>>>(bufB, W_emb, bufA);
    k_agg<<<N / 8, 256>>>(bufA, bufB, b_emb);

    // pool (assignment branch collapses to mean/K) + MLP head
    k_pool<<<BBG, 512>>>(bufB);
    k_mlp<<<BBG, 128>>>(W1, b1, W2, b2, out);
}